// round 1
// baseline (speedup 1.0000x reference)
#include <cuda_runtime.h>
#include <math.h>

// ---------------------------------------------------------------------------
// Problem constants
// ---------------------------------------------------------------------------
#define BATCH      8
#define T_FRAMES   2048
#define M_TOTAL    (BATCH * T_FRAMES)   // 16384 frames
#define K_DIM      512
#define N_DIM      1026                 // N_FFT + 2
#define NBINS      513                  // N_FFT/2 + 1
#define NFFT       1024
#define HOP        256
#define PAD        384                  // (1024-256)/2
#define OUT_FULL   ((T_FRAMES - 1) * HOP + NFFT)  // 525312
#define OUT_LEN    (OUT_FULL - 2 * PAD)           // 524544

// ---------------------------------------------------------------------------
// Scratch (device globals: no runtime allocation allowed)
// ---------------------------------------------------------------------------
__device__ float g_h[M_TOTAL * N_DIM];        // linear head output  (~67 MB)
__device__ float g_frames[M_TOTAL * NFFT];    // windowed iFFT frames (~67 MB)

// ---------------------------------------------------------------------------
// Kernel 1: SGEMM  h = x @ W + b   (M=16384, K=512, N=1026), fp32
// 128x128 block tile, BK=16, 256 threads, 8x8 per-thread microtile.
// ---------------------------------------------------------------------------
#define BM 128
#define BN 128
#define BK 16

__global__ void __launch_bounds__(256, 2)
sgemm_kernel(const float* __restrict__ A,      // [M, K]
             const float* __restrict__ B,      // [K, N]
             const float* __restrict__ bias)   // [N]
{
    __shared__ float As[BK][BM];
    __shared__ float Bs[BK][BN];

    const int tid = threadIdx.x;
    const int bm  = blockIdx.y * BM;
    const int bn  = blockIdx.x * BN;
    const int tx  = tid & 15;     // 0..15 -> N microtile
    const int ty  = tid >> 4;     // 0..15 -> M microtile

    float acc[8][8];
#pragma unroll
    for (int i = 0; i < 8; i++)
#pragma unroll
        for (int j = 0; j < 8; j++) acc[i][j] = 0.0f;

    for (int k0 = 0; k0 < K_DIM; k0 += BK) {
        // ---- load A tile 128x16 (512 float4, 2 per thread), store transposed
        // A row stride 512 floats -> float4 aligned
#pragma unroll
        for (int l = 0; l < 2; l++) {
            int f   = tid + l * 256;
            int row = f >> 2;              // 0..127
            int kc  = (f & 3) << 2;        // 0,4,8,12
            float4 v = *(const float4*)&A[(size_t)(bm + row) * K_DIM + k0 + kc];
            As[kc + 0][row] = v.x;
            As[kc + 1][row] = v.y;
            As[kc + 2][row] = v.z;
            As[kc + 3][row] = v.w;
        }
        // ---- load B tile 16x128 (2 per thread). Row stride 1026 floats is
        // only 8-byte aligned (1026 % 4 == 2) -> use float2 pairs.
#pragma unroll
        for (int l = 0; l < 2; l++) {
            int f    = tid + l * 256;
            int kr   = f >> 5;             // 0..15
            int col  = (f & 31) << 2;      // 0..124 step 4
            int gcol = bn + col;
            const float* brow = &B[(size_t)(k0 + kr) * N_DIM];
            float4 v;
            if (gcol + 3 < N_DIM) {
                float2 lo = *(const float2*)&brow[gcol];
                float2 hi = *(const float2*)&brow[gcol + 2];
                v = make_float4(lo.x, lo.y, hi.x, hi.y);
            } else {
                v.x = (gcol + 0 < N_DIM) ? brow[gcol + 0] : 0.0f;
                v.y = (gcol + 1 < N_DIM) ? brow[gcol + 1] : 0.0f;
                v.z = (gcol + 2 < N_DIM) ? brow[gcol + 2] : 0.0f;
                v.w = (gcol + 3 < N_DIM) ? brow[gcol + 3] : 0.0f;
            }
            *(float4*)&Bs[kr][col] = v;
        }
        __syncthreads();

#pragma unroll
        for (int kk = 0; kk < BK; kk++) {
            float4 a0 = *(float4*)&As[kk][ty * 8];
            float4 a1 = *(float4*)&As[kk][ty * 8 + 4];
            float4 b0 = *(float4*)&Bs[kk][tx * 8];
            float4 b1 = *(float4*)&Bs[kk][tx * 8 + 4];
            float a[8] = {a0.x, a0.y, a0.z, a0.w, a1.x, a1.y, a1.z, a1.w};
            float b[8] = {b0.x, b0.y, b0.z, b0.w, b1.x, b1.y, b1.z, b1.w};
#pragma unroll
            for (int i = 0; i < 8; i++)
#pragma unroll
                for (int j = 0; j < 8; j++)
                    acc[i][j] = fmaf(a[i], b[j], acc[i][j]);
        }
        __syncthreads();
    }

    // ---- epilogue: add bias, store h
#pragma unroll
    for (int i = 0; i < 8; i++) {
        int row = bm + ty * 8 + i;
        float* hrow = &g_h[(size_t)row * N_DIM];
#pragma unroll
        for (int j = 0; j < 8; j++) {
            int col = bn + tx * 8 + j;
            if (col < N_DIM) hrow[col] = acc[i][j] + bias[col];
        }
    }
}

// ---------------------------------------------------------------------------
// Kernel 2: per-frame spectrum -> 1024-pt inverse complex FFT (Hermitian
// extension, real part == irfft) -> Hann window -> g_frames.
// One block of 256 threads per frame, FFT in shared memory.
// ---------------------------------------------------------------------------
__global__ void __launch_bounds__(256)
ifft_kernel()
{
    __shared__ float2 data[NFFT];        // 8 KB
    __shared__ float2 spec[NBINS];       // ~4.1 KB
    __shared__ float2 tw[NFFT / 2];      // 4 KB  twiddles e^{+i 2 pi j / 1024}

    const int f   = blockIdx.x;          // frame id 0..16383
    const int tid = threadIdx.x;
    const float* __restrict__ h = g_h + (size_t)f * N_DIM;

    // spectrum: S_k = min(exp(h_k),100) * (cos p_k + i sin p_k)
    for (int k = tid; k < NBINS; k += 256) {
        float mag = fminf(expf(h[k]), 100.0f);
        float s, c;
        sincosf(h[NBINS + k], &s, &c);
        spec[k] = make_float2(mag * c, mag * s);
    }
    // twiddles (inverse FFT sign: +i)
    for (int j = tid; j < NFFT / 2; j += 256) {
        float s, c;
        sincospif((float)j * (1.0f / 512.0f), &s, &c);   // angle = 2*pi*j/1024
        tw[j] = make_float2(c, s);
    }
    __syncthreads();

    // bit-reversed load with Hermitian extension X[1024-k] = conj(X[k])
    for (int i = tid; i < NFFT; i += 256) {
        int r = __brev((unsigned)i) >> 22;   // 10-bit reverse
        float2 v;
        if (r <= NFFT / 2) {
            v = spec[r];
        } else {
            float2 u = spec[NFFT - r];
            v = make_float2(u.x, -u.y);
        }
        data[i] = v;
    }
    __syncthreads();

    // 10 radix-2 DIT stages
#pragma unroll
    for (int s = 1; s <= 10; s++) {
        const int half   = 1 << (s - 1);
        const int tshift = 10 - s;
#pragma unroll
        for (int l = 0; l < 2; l++) {
            int idx = tid + l * 256;             // butterfly 0..511
            int j   = idx & (half - 1);
            int grp = idx >> (s - 1);
            int pos = (grp << s) + j;
            float2 w  = tw[j << tshift];
            float2 lo = data[pos];
            float2 hi = data[pos + half];
            float2 t  = make_float2(w.x * hi.x - w.y * hi.y,
                                    w.x * hi.y + w.y * hi.x);
            data[pos]        = make_float2(lo.x + t.x, lo.y + t.y);
            data[pos + half] = make_float2(lo.x - t.x, lo.y - t.y);
        }
        __syncthreads();
    }

    // scale 1/N, window, store real part
    const float inv = 1.0f / (float)NFFT;
    float* __restrict__ fr = g_frames + (size_t)f * NFFT;
    for (int n = tid; n < NFFT; n += 256) {
        float win = 0.5f * (1.0f - cospif((float)n * (1.0f / 512.0f)));
        fr[n] = data[n].x * inv * win;
    }
}

// ---------------------------------------------------------------------------
// Kernel 3: overlap-add (gather form) + envelope normalization.
// Each output sample sums <=4 overlapping windowed frames; env is the sum of
// win^2 at the same taps (matches reference exactly: same t-range).
// ---------------------------------------------------------------------------
__global__ void __launch_bounds__(256)
ola_kernel(float* __restrict__ out)
{
    int i = blockIdx.x * blockDim.x + threadIdx.x;
    if (i >= BATCH * OUT_LEN) return;
    int b  = i / OUT_LEN;
    int mo = i - b * OUT_LEN;
    int m  = mo + PAD;

    int t_hi = m >> 8;                       // m / HOP
    if (t_hi > T_FRAMES - 1) t_hi = T_FRAMES - 1;
    int t_lo = (m >= (NFFT - HOP)) ? ((m - (NFFT - HOP)) >> 8) : 0;

    float acc = 0.0f, env = 0.0f;
    const float* __restrict__ base = g_frames + (size_t)b * T_FRAMES * NFFT;
#pragma unroll 4
    for (int t = t_lo; t <= t_hi; t++) {
        int n = m - (t << 8);                // 0..1023
        float win = 0.5f * (1.0f - cospif((float)n * (1.0f / 512.0f)));
        acc += base[(size_t)t * NFFT + n];
        env += win * win;
    }
    out[i] = acc / env;
}

// ---------------------------------------------------------------------------
// Launch
// ---------------------------------------------------------------------------
extern "C" void kernel_launch(void* const* d_in, const int* in_sizes, int n_in,
                              void* d_out, int out_size)
{
    const float* x    = (const float*)d_in[0];   // [8, 2048, 512]
    const float* W    = (const float*)d_in[1];   // [512, 1026]
    const float* bias = (const float*)d_in[2];   // [1026]
    float* out = (float*)d_out;                  // [8, 524544]

    // 1) GEMM -> g_h
    dim3 g1((N_DIM + BN - 1) / BN, M_TOTAL / BM);  // (9, 128)
    sgemm_kernel<<<g1, 256>>>(x, W, bias);

    // 2) spectrum -> irfft -> window -> g_frames
    ifft_kernel<<<M_TOTAL, 256>>>();

    // 3) overlap-add + env normalize -> out
    int total = BATCH * OUT_LEN;
    ola_kernel<<<(total + 255) / 256, 256>>>(out);
}

// round 3
// speedup vs baseline: 1.8041x; 1.8041x over previous
#include <cuda_runtime.h>
#include <cuda_bf16.h>
#include <math.h>
#include <stdint.h>

// ---------------------------------------------------------------------------
// Problem constants
// ---------------------------------------------------------------------------
#define BATCH      8
#define T_FRAMES   2048
#define M_TOTAL    (BATCH * T_FRAMES)   // 16384 frames
#define K_DIM      512
#define N_DIM      1026                 // N_FFT + 2
#define N_PAD      1152                 // 9 * 128
#define NBINS      513                  // N_FFT/2 + 1
#define NFFT       1024
#define HOP        256
#define PAD        384                  // (1024-256)/2
#define OUT_FULL   ((T_FRAMES - 1) * HOP + NFFT)  // 525312
#define OUT_LEN    (OUT_FULL - 2 * PAD)           // 524544

// ---------------------------------------------------------------------------
// Scratch (device globals: no runtime allocation allowed)
// ---------------------------------------------------------------------------
__device__ float g_h[(size_t)M_TOTAL * N_DIM];        // linear head output (~67 MB)
__device__ float g_frames[(size_t)M_TOTAL * NFFT];    // windowed iFFT frames (~67 MB)
__device__ __nv_bfloat16 g_xhi[(size_t)M_TOTAL * K_DIM];  // 16.8 MB
__device__ __nv_bfloat16 g_xlo[(size_t)M_TOTAL * K_DIM];  // 16.8 MB
__device__ __nv_bfloat16 g_wthi[(size_t)N_PAD * K_DIM];   // W^T hi, padded
__device__ __nv_bfloat16 g_wtlo[(size_t)N_PAD * K_DIM];   // W^T lo, padded

// ---------------------------------------------------------------------------
// baseline-arch PTX helpers (all supported on compute_103 WITHOUT 'a')
// ---------------------------------------------------------------------------
__device__ __forceinline__ uint32_t smem_u32(const void* p) {
    return (uint32_t)__cvta_generic_to_shared(p);
}

__device__ __forceinline__ void cp_async16(uint32_t saddr, const void* gptr) {
    asm volatile("cp.async.cg.shared.global [%0], [%1], 16;"
                 :: "r"(saddr), "l"(gptr));
}
#define CP_COMMIT() asm volatile("cp.async.commit_group;" ::: "memory")
#define CP_WAIT0()  asm volatile("cp.async.wait_group 0;" ::: "memory")

#define LDSM_X4(r0, r1, r2, r3, addr) \
    asm volatile("ldmatrix.sync.aligned.m8n8.x4.shared.b16 {%0,%1,%2,%3}, [%4];" \
                 : "=r"(r0), "=r"(r1), "=r"(r2), "=r"(r3) : "r"(addr))

#define MMA16816(c, a0, a1, a2, a3, b0, b1) \
    asm volatile("mma.sync.aligned.m16n8k16.row.col.f32.bf16.bf16.f32 " \
                 "{%0,%1,%2,%3}, {%4,%5,%6,%7}, {%8,%9}, {%0,%1,%2,%3};" \
                 : "+f"((c)[0]), "+f"((c)[1]), "+f"((c)[2]), "+f"((c)[3]) \
                 : "r"(a0), "r"(a1), "r"(a2), "r"(a3), "r"(b0), "r"(b1))

// ---------------------------------------------------------------------------
// Prep kernel 1: split x (fp32) into bf16 hi/lo
// ---------------------------------------------------------------------------
__global__ void __launch_bounds__(256)
split_x_kernel(const float* __restrict__ x)
{
    size_t i = ((size_t)blockIdx.x * 256 + threadIdx.x) * 8;   // 8 floats / thread
    float4 a = *(const float4*)(x + i);
    float4 b = *(const float4*)(x + i + 4);
    float v[8] = {a.x, a.y, a.z, a.w, b.x, b.y, b.z, b.w};
    union { __nv_bfloat16 h[8]; uint4 u; } H, L;
#pragma unroll
    for (int j = 0; j < 8; j++) {
        __nv_bfloat16 hi = __float2bfloat16(v[j]);
        H.h[j] = hi;
        L.h[j] = __float2bfloat16(v[j] - __bfloat162float(hi));
    }
    *(uint4*)&g_xhi[i] = H.u;
    *(uint4*)&g_xlo[i] = L.u;
}

// ---------------------------------------------------------------------------
// Prep kernel 2: W [K, 1026] -> Wt hi/lo [1152, 512] bf16 (transposed, padded)
// ---------------------------------------------------------------------------
__global__ void __launch_bounds__(256)
prep_w_kernel(const float* __restrict__ W)
{
    int idx = blockIdx.x * 256 + threadIdx.x;       // over N_PAD * K_DIM
    if (idx >= N_PAD * K_DIM) return;
    int n = idx >> 9;          // 0..1151
    int k = idx & 511;
    float v = (n < N_DIM) ? W[(size_t)k * N_DIM + n] : 0.0f;
    __nv_bfloat16 hi = __float2bfloat16(v);
    g_wthi[idx] = hi;
    g_wtlo[idx] = __float2bfloat16(v - __bfloat162float(hi));
}

// ---------------------------------------------------------------------------
// Kernel 1: HMMA GEMM  h = x @ W + b  via 3x-bf16 split on mma.sync.m16n8k16.
// CTA tile 128(M) x 128(N), BK=64, 8 warps (warp tile 64x32), cp.async
// 2-stage pipeline, SW128 xor swizzle in SMEM.
// ---------------------------------------------------------------------------
// Per stage: 4 matrices (Ah, Al, Bh, Bl), each 128 rows x 64 bf16 = 16 KB.
#define MAT_BYTES   16384
#define STAGE_BYTES 65536
#define GEMM_SMEM   (2 * STAGE_BYTES)     // 128 KB

__device__ __forceinline__ void load_stage(uint32_t sdst,
                                           const __nv_bfloat16* const* srcs,
                                           int k0, int tid)
{
#pragma unroll
    for (int m = 0; m < 4; m++) {
        const __nv_bfloat16* __restrict__ src = srcs[m] + k0;
#pragma unroll
        for (int t = 0; t < 4; t++) {
            int idx = tid + (t << 8);          // 0..1023
            int row = idx >> 3;                // 0..127
            int g   = idx & 7;                 // 16B granule within 128B row
            uint32_t saddr = sdst + (m << 14) + (row << 7) + ((g ^ (row & 7)) << 4);
            cp_async16(saddr, src + (size_t)row * K_DIM + (g << 3));
        }
    }
}

__global__ void __launch_bounds__(256)
gemm_mma_kernel(const float* __restrict__ bias)
{
    extern __shared__ __align__(128) char smem[];
    const int tid  = threadIdx.x;
    const int lane = tid & 31;
    const int warp = tid >> 5;
    const int wm   = (warp >> 2) << 6;   // 0 / 64
    const int wn   = (warp & 3) << 5;    // 0,32,64,96
    const int bm   = blockIdx.y << 7;
    const int bn   = blockIdx.x << 7;
    const uint32_t sbase = smem_u32(smem);

    const __nv_bfloat16* srcs[4] = {
        g_xhi  + (size_t)bm * K_DIM,
        g_xlo  + (size_t)bm * K_DIM,
        g_wthi + (size_t)bn * K_DIM,
        g_wtlo + (size_t)bn * K_DIM
    };

    float acc[4][4][4];
#pragma unroll
    for (int i = 0; i < 4; i++)
#pragma unroll
        for (int j = 0; j < 4; j++)
#pragma unroll
            for (int r = 0; r < 4; r++) acc[i][j][r] = 0.0f;

    // precomputed fragment address offsets (within a matrix, swizzled)
    // A: row = wm + i*16 + (lane&15), k granule base adds (lane>>4)
    const int a_row  = wm + (lane & 15);
    const int a_gadd = (lane >> 4);                 // 0/1 -> +8 in k
    // B: row = wn + j2*16 + (lane&7) + (lane>>4)*8, k granule adds ((lane>>3)&1)
    const int b_row  = wn + (lane & 7) + ((lane >> 4) << 3);
    const int b_gadd = ((lane >> 3) & 1);

    // prologue: stage 0
    load_stage(sbase, srcs, 0, tid);
    CP_COMMIT();

    for (int ck = 0; ck < K_DIM / 64; ck++) {       // 8 chunks
        CP_WAIT0();
        __syncthreads();
        if (ck + 1 < K_DIM / 64)
            load_stage(sbase + (((ck + 1) & 1) ? STAGE_BYTES : 0), srcs,
                       (ck + 1) << 6, tid);
        CP_COMMIT();

        const uint32_t stg = sbase + ((ck & 1) ? STAGE_BYTES : 0);

#pragma unroll
        for (int s16 = 0; s16 < 4; s16++) {         // 4 x k16 per chunk
            const int g0 = (s16 << 1);              // granule base (kk/8)
            uint32_t a[4][4], bh[2][4], bl[2][4];

            // ---- A(hi) fragments: 4 ldmatrix.x4
#pragma unroll
            for (int i = 0; i < 4; i++) {
                int row = a_row + (i << 4);
                int g   = g0 + a_gadd;
                uint32_t addr = stg + (row << 7) + ((g ^ (row & 7)) << 4);
                LDSM_X4(a[i][0], a[i][1], a[i][2], a[i][3], addr);
            }
            // ---- B(hi) and B(lo) fragments: 2+2 ldmatrix.x4
#pragma unroll
            for (int j2 = 0; j2 < 2; j2++) {
                int row = b_row + (j2 << 4);
                int g   = g0 + b_gadd;
                uint32_t boff = (row << 7) + ((g ^ (row & 7)) << 4);
                LDSM_X4(bh[j2][0], bh[j2][1], bh[j2][2], bh[j2][3],
                        stg + 2 * MAT_BYTES + boff);
                LDSM_X4(bl[j2][0], bl[j2][1], bl[j2][2], bl[j2][3],
                        stg + 3 * MAT_BYTES + boff);
            }
            // ---- pass 1: Ah x Bh
#pragma unroll
            for (int i = 0; i < 4; i++)
#pragma unroll
                for (int j = 0; j < 4; j++)
                    MMA16816(acc[i][j], a[i][0], a[i][1], a[i][2], a[i][3],
                             bh[j >> 1][(j & 1) << 1], bh[j >> 1][((j & 1) << 1) + 1]);
            // ---- pass 2: Ah x Bl
#pragma unroll
            for (int i = 0; i < 4; i++)
#pragma unroll
                for (int j = 0; j < 4; j++)
                    MMA16816(acc[i][j], a[i][0], a[i][1], a[i][2], a[i][3],
                             bl[j >> 1][(j & 1) << 1], bl[j >> 1][((j & 1) << 1) + 1]);
            // ---- A(lo) fragments (reuse registers)
#pragma unroll
            for (int i = 0; i < 4; i++) {
                int row = a_row + (i << 4);
                int g   = g0 + a_gadd;
                uint32_t addr = stg + MAT_BYTES + (row << 7) + ((g ^ (row & 7)) << 4);
                LDSM_X4(a[i][0], a[i][1], a[i][2], a[i][3], addr);
            }
            // ---- pass 3: Al x Bh
#pragma unroll
            for (int i = 0; i < 4; i++)
#pragma unroll
                for (int j = 0; j < 4; j++)
                    MMA16816(acc[i][j], a[i][0], a[i][1], a[i][2], a[i][3],
                             bh[j >> 1][(j & 1) << 1], bh[j >> 1][((j & 1) << 1) + 1]);
        }
    }

    // ---- epilogue: bias + direct float2 stores
    const int r0 = bm + wm + (lane >> 2);
    const int c0 = bn + wn + ((lane & 3) << 1);
#pragma unroll
    for (int j = 0; j < 4; j++) {
        int col = c0 + (j << 3);
        if (col < N_DIM) {
            float bx = bias[col];
            float by = bias[col + 1];
#pragma unroll
            for (int i = 0; i < 4; i++) {
                int row = r0 + (i << 4);
                *(float2*)&g_h[(size_t)row * N_DIM + col] =
                    make_float2(acc[i][j][0] + bx, acc[i][j][1] + by);
                *(float2*)&g_h[(size_t)(row + 8) * N_DIM + col] =
                    make_float2(acc[i][j][2] + bx, acc[i][j][3] + by);
            }
        }
    }
}

// ---------------------------------------------------------------------------
// Kernel 2: per-frame spectrum -> 1024-pt inverse FFT (Hermitian) -> window
// ---------------------------------------------------------------------------
__global__ void __launch_bounds__(256)
ifft_kernel()
{
    __shared__ float2 data[NFFT];        // 8 KB
    __shared__ float2 spec[NBINS];       // ~4.1 KB
    __shared__ float2 tw[NFFT / 2];      // 4 KB

    const int f   = blockIdx.x;
    const int tid = threadIdx.x;
    const float* __restrict__ h = g_h + (size_t)f * N_DIM;

    for (int k = tid; k < NBINS; k += 256) {
        float mag = fminf(expf(h[k]), 100.0f);
        float s, c;
        sincosf(h[NBINS + k], &s, &c);
        spec[k] = make_float2(mag * c, mag * s);
    }
    for (int j = tid; j < NFFT / 2; j += 256) {
        float s, c;
        sincospif((float)j * (1.0f / 512.0f), &s, &c);
        tw[j] = make_float2(c, s);
    }
    __syncthreads();

    for (int i = tid; i < NFFT; i += 256) {
        int r = __brev((unsigned)i) >> 22;
        float2 v;
        if (r <= NFFT / 2) {
            v = spec[r];
        } else {
            float2 u = spec[NFFT - r];
            v = make_float2(u.x, -u.y);
        }
        data[i] = v;
    }
    __syncthreads();

#pragma unroll
    for (int s = 1; s <= 10; s++) {
        const int half   = 1 << (s - 1);
        const int tshift = 10 - s;
#pragma unroll
        for (int l = 0; l < 2; l++) {
            int idx = tid + l * 256;
            int j   = idx & (half - 1);
            int grp = idx >> (s - 1);
            int pos = (grp << s) + j;
            float2 w  = tw[j << tshift];
            float2 lo = data[pos];
            float2 hi = data[pos + half];
            float2 t  = make_float2(w.x * hi.x - w.y * hi.y,
                                    w.x * hi.y + w.y * hi.x);
            data[pos]        = make_float2(lo.x + t.x, lo.y + t.y);
            data[pos + half] = make_float2(lo.x - t.x, lo.y - t.y);
        }
        __syncthreads();
    }

    const float inv = 1.0f / (float)NFFT;
    float* __restrict__ fr = g_frames + (size_t)f * NFFT;
    for (int n = tid; n < NFFT; n += 256) {
        float win = 0.5f * (1.0f - cospif((float)n * (1.0f / 512.0f)));
        fr[n] = data[n].x * inv * win;
    }
}

// ---------------------------------------------------------------------------
// Kernel 3: overlap-add (gather) + envelope normalization
// ---------------------------------------------------------------------------
__global__ void __launch_bounds__(256)
ola_kernel(float* __restrict__ out)
{
    int i = blockIdx.x * blockDim.x + threadIdx.x;
    if (i >= BATCH * OUT_LEN) return;
    int b  = i / OUT_LEN;
    int mo = i - b * OUT_LEN;
    int m  = mo + PAD;

    int t_hi = m >> 8;
    if (t_hi > T_FRAMES - 1) t_hi = T_FRAMES - 1;
    int t_lo = (m >= (NFFT - HOP)) ? ((m - (NFFT - HOP)) >> 8) : 0;

    float acc = 0.0f, env = 0.0f;
    const float* __restrict__ base = g_frames + (size_t)b * T_FRAMES * NFFT;
#pragma unroll 4
    for (int t = t_lo; t <= t_hi; t++) {
        int n = m - (t << 8);
        float win = 0.5f * (1.0f - cospif((float)n * (1.0f / 512.0f)));
        acc += base[(size_t)t * NFFT + n];
        env += win * win;
    }
    out[i] = acc / env;
}

// ---------------------------------------------------------------------------
// Launch
// ---------------------------------------------------------------------------
extern "C" void kernel_launch(void* const* d_in, const int* in_sizes, int n_in,
                              void* d_out, int out_size)
{
    const float* x    = (const float*)d_in[0];   // [8, 2048, 512]
    const float* W    = (const float*)d_in[1];   // [512, 1026]
    const float* bias = (const float*)d_in[2];   // [1026]
    float* out = (float*)d_out;                  // [8, 524544]

    cudaFuncSetAttribute(gemm_mma_kernel,
                         cudaFuncAttributeMaxDynamicSharedMemorySize,
                         GEMM_SMEM);

    // 0) split inputs into bf16 hi/lo
    split_x_kernel<<<(M_TOTAL * K_DIM) / (256 * 8), 256>>>(x);
    prep_w_kernel<<<(N_PAD * K_DIM + 255) / 256, 256>>>(W);

    // 1) tensor-core (HMMA) GEMM -> g_h
    dim3 g1(N_PAD / 128, M_TOTAL / 128);   // (9, 128)
    gemm_mma_kernel<<<g1, 256, GEMM_SMEM>>>(bias);

    // 2) spectrum -> irfft -> window -> g_frames
    ifft_kernel<<<M_TOTAL, 256>>>();

    // 3) overlap-add + env normalize -> out
    int total = BATCH * OUT_LEN;
    ola_kernel<<<(total + 255) / 256, 256>>>(out);
}

// round 5
// speedup vs baseline: 2.2951x; 1.2722x over previous
#include <cuda_runtime.h>
#include <cuda_bf16.h>
#include <math.h>
#include <stdint.h>

// ---------------------------------------------------------------------------
// Problem constants
// ---------------------------------------------------------------------------
#define BATCH      8
#define T_FRAMES   2048
#define M_TOTAL    (BATCH * T_FRAMES)   // 16384 frames
#define K_DIM      512
#define N_DIM      1026                 // N_FFT + 2
#define N_PAD      1152                 // 9 * 128
#define NBINS      513                  // N_FFT/2 + 1
#define NFFT       1024
#define HOP        256
#define PAD        384                  // (1024-256)/2
#define OUT_FULL   ((T_FRAMES - 1) * HOP + NFFT)  // 525312
#define OUT_LEN    (OUT_FULL - 2 * PAD)           // 524544

// ---------------------------------------------------------------------------
// Scratch (device globals: no runtime allocation allowed)
// ---------------------------------------------------------------------------
__device__ float g_h[(size_t)M_TOTAL * N_DIM];        // linear head output (~67 MB)
__device__ float g_frames[(size_t)M_TOTAL * NFFT];    // windowed iFFT frames (~67 MB)
__device__ __nv_bfloat16 g_xhi[(size_t)M_TOTAL * K_DIM];
__device__ __nv_bfloat16 g_xlo[(size_t)M_TOTAL * K_DIM];
__device__ __nv_bfloat16 g_wthi[(size_t)N_PAD * K_DIM];
__device__ __nv_bfloat16 g_wtlo[(size_t)N_PAD * K_DIM];
// precomputed tables
__device__ float2 g_tw[256];        // e^{+2*pi*i*j/512},  j<256  (FFT twiddles)
__device__ float2 g_pretw[512];     // e^{+2*pi*i*k/1024}, k<512  (packing twiddles)
__device__ float  g_win[NFFT];      // hann window
__device__ float  g_env_inv[OUT_FULL];  // 1 / sum win^2

// ---------------------------------------------------------------------------
// baseline-arch PTX helpers (supported on compute_103 WITHOUT 'a')
// ---------------------------------------------------------------------------
__device__ __forceinline__ uint32_t smem_u32(const void* p) {
    return (uint32_t)__cvta_generic_to_shared(p);
}

__device__ __forceinline__ void cp_async16(uint32_t saddr, const void* gptr) {
    asm volatile("cp.async.cg.shared.global [%0], [%1], 16;"
                 :: "r"(saddr), "l"(gptr));
}
#define CP_COMMIT() asm volatile("cp.async.commit_group;" ::: "memory")
#define CP_WAIT0()  asm volatile("cp.async.wait_group 0;" ::: "memory")

#define LDSM_X4(r0, r1, r2, r3, addr) \
    asm volatile("ldmatrix.sync.aligned.m8n8.x4.shared.b16 {%0,%1,%2,%3}, [%4];" \
                 : "=r"(r0), "=r"(r1), "=r"(r2), "=r"(r3) : "r"(addr))

#define MMA16816(c, a0, a1, a2, a3, b0, b1) \
    asm volatile("mma.sync.aligned.m16n8k16.row.col.f32.bf16.bf16.f32 " \
                 "{%0,%1,%2,%3}, {%4,%5,%6,%7}, {%8,%9}, {%0,%1,%2,%3};" \
                 : "+f"((c)[0]), "+f"((c)[1]), "+f"((c)[2]), "+f"((c)[3]) \
                 : "r"(a0), "r"(a1), "r"(a2), "r"(a3), "r"(b0), "r"(b1))

// ---------------------------------------------------------------------------
// Prep: split x (fp32) into bf16 hi/lo
// ---------------------------------------------------------------------------
__global__ void __launch_bounds__(256)
split_x_kernel(const float* __restrict__ x)
{
    size_t i = ((size_t)blockIdx.x * 256 + threadIdx.x) * 8;
    float4 a = *(const float4*)(x + i);
    float4 b = *(const float4*)(x + i + 4);
    float v[8] = {a.x, a.y, a.z, a.w, b.x, b.y, b.z, b.w};
    union { __nv_bfloat16 h[8]; uint4 u; } H, L;
#pragma unroll
    for (int j = 0; j < 8; j++) {
        __nv_bfloat16 hi = __float2bfloat16(v[j]);
        H.h[j] = hi;
        L.h[j] = __float2bfloat16(v[j] - __bfloat162float(hi));
    }
    *(uint4*)&g_xhi[i] = H.u;
    *(uint4*)&g_xlo[i] = L.u;
}

// ---------------------------------------------------------------------------
// Prep: W [K, 1026] -> Wt hi/lo [1152, 512] bf16 (transposed, padded)
// ---------------------------------------------------------------------------
__global__ void __launch_bounds__(256)
prep_w_kernel(const float* __restrict__ W)
{
    int idx = blockIdx.x * 256 + threadIdx.x;
    if (idx >= N_PAD * K_DIM) return;
    int n = idx >> 9;
    int k = idx & 511;
    float v = (n < N_DIM) ? W[(size_t)k * N_DIM + n] : 0.0f;
    __nv_bfloat16 hi = __float2bfloat16(v);
    g_wthi[idx] = hi;
    g_wtlo[idx] = __float2bfloat16(v - __bfloat162float(hi));
}

// ---------------------------------------------------------------------------
// Prep: trig tables (twiddles, packing twiddles, hann window)
// ---------------------------------------------------------------------------
__global__ void __launch_bounds__(256)
tables_kernel()
{
    int i = blockIdx.x * 256 + threadIdx.x;     // 0..1023
    float s, c;
    if (i < 256) {                               // e^{2*pi*i*j/512}
        sincospif((float)i * (1.0f / 256.0f), &s, &c);
        g_tw[i] = make_float2(c, s);
    }
    if (i < 512) {                               // e^{2*pi*i*k/1024}
        sincospif((float)i * (1.0f / 512.0f), &s, &c);
        g_pretw[i] = make_float2(c, s);
    }
    if (i < NFFT) {
        g_win[i] = 0.5f * (1.0f - cospif((float)i * (1.0f / 512.0f)));
    }
}

// ---------------------------------------------------------------------------
// Prep: envelope reciprocal (batch-independent)
// ---------------------------------------------------------------------------
__global__ void __launch_bounds__(256)
env_kernel()
{
    int m = blockIdx.x * 256 + threadIdx.x;
    if (m >= OUT_FULL) return;
    int t_hi = m >> 8;
    if (t_hi > T_FRAMES - 1) t_hi = T_FRAMES - 1;
    int t_lo = (m >= (NFFT - HOP)) ? ((m - (NFFT - HOP)) >> 8) : 0;
    float env = 0.0f;
    for (int t = t_lo; t <= t_hi; t++) {
        int n = m - (t << 8);
        float win = 0.5f * (1.0f - cospif((float)n * (1.0f / 512.0f)));
        env += win * win;
    }
    g_env_inv[m] = (env > 0.0f) ? (1.0f / env) : 0.0f;
}

// ---------------------------------------------------------------------------
// Kernel 1: HMMA GEMM  h = x @ W + b  via 3x-bf16 split on mma.sync.m16n8k16.
// ---------------------------------------------------------------------------
#define MAT_BYTES   16384
#define STAGE_BYTES 65536
#define GEMM_SMEM   (2 * STAGE_BYTES)     // 128 KB

__device__ __forceinline__ void load_stage(uint32_t sdst,
                                           const __nv_bfloat16* const* srcs,
                                           int k0, int tid)
{
#pragma unroll
    for (int m = 0; m < 4; m++) {
        const __nv_bfloat16* __restrict__ src = srcs[m] + k0;
#pragma unroll
        for (int t = 0; t < 4; t++) {
            int idx = tid + (t << 8);
            int row = idx >> 3;
            int g   = idx & 7;
            uint32_t saddr = sdst + (m << 14) + (row << 7) + ((g ^ (row & 7)) << 4);
            cp_async16(saddr, src + (size_t)row * K_DIM + (g << 3));
        }
    }
}

__global__ void __launch_bounds__(256)
gemm_mma_kernel(const float* __restrict__ bias)
{
    extern __shared__ __align__(128) char smem[];
    const int tid  = threadIdx.x;
    const int lane = tid & 31;
    const int warp = tid >> 5;
    const int wm   = (warp >> 2) << 6;
    const int wn   = (warp & 3) << 5;
    const int bm   = blockIdx.y << 7;
    const int bn   = blockIdx.x << 7;
    const uint32_t sbase = smem_u32(smem);

    const __nv_bfloat16* srcs[4] = {
        g_xhi  + (size_t)bm * K_DIM,
        g_xlo  + (size_t)bm * K_DIM,
        g_wthi + (size_t)bn * K_DIM,
        g_wtlo + (size_t)bn * K_DIM
    };

    float acc[4][4][4];
#pragma unroll
    for (int i = 0; i < 4; i++)
#pragma unroll
        for (int j = 0; j < 4; j++)
#pragma unroll
            for (int r = 0; r < 4; r++) acc[i][j][r] = 0.0f;

    const int a_row  = wm + (lane & 15);
    const int a_gadd = (lane >> 4);
    const int b_row  = wn + (lane & 7) + ((lane >> 4) << 3);
    const int b_gadd = ((lane >> 3) & 1);

    load_stage(sbase, srcs, 0, tid);
    CP_COMMIT();

    for (int ck = 0; ck < K_DIM / 64; ck++) {
        CP_WAIT0();
        __syncthreads();
        if (ck + 1 < K_DIM / 64)
            load_stage(sbase + (((ck + 1) & 1) ? STAGE_BYTES : 0), srcs,
                       (ck + 1) << 6, tid);
        CP_COMMIT();

        const uint32_t stg = sbase + ((ck & 1) ? STAGE_BYTES : 0);

#pragma unroll
        for (int s16 = 0; s16 < 4; s16++) {
            const int g0 = (s16 << 1);
            uint32_t a[4][4], bh[2][4], bl[2][4];

#pragma unroll
            for (int i = 0; i < 4; i++) {
                int row = a_row + (i << 4);
                int g   = g0 + a_gadd;
                uint32_t addr = stg + (row << 7) + ((g ^ (row & 7)) << 4);
                LDSM_X4(a[i][0], a[i][1], a[i][2], a[i][3], addr);
            }
#pragma unroll
            for (int j2 = 0; j2 < 2; j2++) {
                int row = b_row + (j2 << 4);
                int g   = g0 + b_gadd;
                uint32_t boff = (row << 7) + ((g ^ (row & 7)) << 4);
                LDSM_X4(bh[j2][0], bh[j2][1], bh[j2][2], bh[j2][3],
                        stg + 2 * MAT_BYTES + boff);
                LDSM_X4(bl[j2][0], bl[j2][1], bl[j2][2], bl[j2][3],
                        stg + 3 * MAT_BYTES + boff);
            }
#pragma unroll
            for (int i = 0; i < 4; i++)
#pragma unroll
                for (int j = 0; j < 4; j++)
                    MMA16816(acc[i][j], a[i][0], a[i][1], a[i][2], a[i][3],
                             bh[j >> 1][(j & 1) << 1], bh[j >> 1][((j & 1) << 1) + 1]);
#pragma unroll
            for (int i = 0; i < 4; i++)
#pragma unroll
                for (int j = 0; j < 4; j++)
                    MMA16816(acc[i][j], a[i][0], a[i][1], a[i][2], a[i][3],
                             bl[j >> 1][(j & 1) << 1], bl[j >> 1][((j & 1) << 1) + 1]);
#pragma unroll
            for (int i = 0; i < 4; i++) {
                int row = a_row + (i << 4);
                int g   = g0 + a_gadd;
                uint32_t addr = stg + MAT_BYTES + (row << 7) + ((g ^ (row & 7)) << 4);
                LDSM_X4(a[i][0], a[i][1], a[i][2], a[i][3], addr);
            }
#pragma unroll
            for (int i = 0; i < 4; i++)
#pragma unroll
                for (int j = 0; j < 4; j++)
                    MMA16816(acc[i][j], a[i][0], a[i][1], a[i][2], a[i][3],
                             bh[j >> 1][(j & 1) << 1], bh[j >> 1][((j & 1) << 1) + 1]);
        }
    }

    const int r0 = bm + wm + (lane >> 2);
    const int c0 = bn + wn + ((lane & 3) << 1);
#pragma unroll
    for (int j = 0; j < 4; j++) {
        int col = c0 + (j << 3);
        if (col < N_DIM) {
            float bx = bias[col];
            float by = bias[col + 1];
#pragma unroll
            for (int i = 0; i < 4; i++) {
                int row = r0 + (i << 4);
                *(float2*)&g_h[(size_t)row * N_DIM + col] =
                    make_float2(acc[i][j][0] + bx, acc[i][j][1] + by);
                *(float2*)&g_h[(size_t)(row + 8) * N_DIM + col] =
                    make_float2(acc[i][j][2] + bx, acc[i][j][3] + by);
            }
        }
    }
}

// ---------------------------------------------------------------------------
// Kernel 2: per-frame spectrum -> HALF-SIZE (512-pt) complex inverse FFT via
// Hermitian packing -> window -> g_frames.
//   E = (X[k]+conj(X[512-k]))/2,  D = (X[k]-conj(X[512-k]))/2,
//   O = e^{+2pi i k/1024} * D,    Z = E + i*O,
//   z = ifft512(Z);  x[2n]=Re z[n], x[2n+1]=Im z[n]
// NOTE: irfft (pocketfft c2r) ignores Im(X[0]) and Im(X[512]) — zero them.
// ---------------------------------------------------------------------------
__global__ void __launch_bounds__(256)
ifft_kernel()
{
    __shared__ float2 spec[NBINS];       // 513 * 8B
    __shared__ float2 data[512];         // 4 KB
    __shared__ float2 tw[256];           // 2 KB

    const int f   = blockIdx.x;
    const int tid = threadIdx.x;
    const float* __restrict__ h = g_h + (size_t)f * N_DIM;

    // spectrum: S_k = min(exp(h_k),100) * (cos p_k + i sin p_k)
    for (int k = tid; k < NBINS; k += 256) {
        float mag = fminf(expf(h[k]), 100.0f);
        float s, c;
        sincosf(h[NBINS + k], &s, &c);
        // DC and Nyquist bins: irfft uses only the real part
        if (k == 0 || k == 512) s = 0.0f;
        spec[k] = make_float2(mag * c, mag * s);
    }
    tw[tid] = g_tw[tid];
    __syncthreads();

    // pack Z and store bit-reversed (9-bit)
#pragma unroll
    for (int l = 0; l < 2; l++) {
        int k = tid + (l << 8);
        float2 Xk = spec[k];
        float2 Xr = spec[512 - k];
        float Ex = 0.5f * (Xk.x + Xr.x);
        float Ey = 0.5f * (Xk.y - Xr.y);
        float Dx = 0.5f * (Xk.x - Xr.x);
        float Dy = 0.5f * (Xk.y + Xr.y);
        float2 w = g_pretw[k];
        float Ox = w.x * Dx - w.y * Dy;
        float Oy = w.x * Dy + w.y * Dx;
        int r = __brev((unsigned)k) >> 23;
        data[r] = make_float2(Ex - Oy, Ey + Ox);
    }
    __syncthreads();

    // 9 radix-2 DIT stages, one butterfly per thread per stage
#pragma unroll
    for (int s = 1; s <= 9; s++) {
        const int half = 1 << (s - 1);
        int j   = tid & (half - 1);
        int pos = ((tid >> (s - 1)) << s) + j;
        float2 w  = tw[j << (9 - s)];
        float2 lo = data[pos];
        float2 hi = data[pos + half];
        float2 t  = make_float2(w.x * hi.x - w.y * hi.y,
                                w.x * hi.y + w.y * hi.x);
        data[pos]        = make_float2(lo.x + t.x, lo.y + t.y);
        data[pos + half] = make_float2(lo.x - t.x, lo.y - t.y);
        __syncthreads();
    }

    // unpack: x[2n] = Re z[n], x[2n+1] = Im z[n]; scale 1/512; window
    const float inv = 1.0f / 512.0f;
    float* __restrict__ fr = g_frames + (size_t)f * NFFT;
#pragma unroll
    for (int l = 0; l < 2; l++) {
        int n = tid + (l << 8);
        float2 z  = data[n];
        float2 w2 = *(const float2*)&g_win[2 * n];
        *(float2*)&fr[2 * n] = make_float2(z.x * inv * w2.x, z.y * inv * w2.y);
    }
}

// ---------------------------------------------------------------------------
// Kernel 3: overlap-add (gather) * precomputed 1/env — no transcendentals
// ---------------------------------------------------------------------------
__global__ void __launch_bounds__(256)
ola_kernel(float* __restrict__ out)
{
    int i = blockIdx.x * blockDim.x + threadIdx.x;
    if (i >= BATCH * OUT_LEN) return;
    int b  = i / OUT_LEN;
    int mo = i - b * OUT_LEN;
    int m  = mo + PAD;

    int t_hi = m >> 8;
    if (t_hi > T_FRAMES - 1) t_hi = T_FRAMES - 1;
    int t_lo = (m >= (NFFT - HOP)) ? ((m - (NFFT - HOP)) >> 8) : 0;

    float acc = 0.0f;
    const float* __restrict__ base = g_frames + (size_t)b * T_FRAMES * NFFT;
#pragma unroll 4
    for (int t = t_lo; t <= t_hi; t++) {
        acc += base[(size_t)t * NFFT + (m - (t << 8))];
    }
    out[i] = acc * g_env_inv[m];
}

// ---------------------------------------------------------------------------
// Launch
// ---------------------------------------------------------------------------
extern "C" void kernel_launch(void* const* d_in, const int* in_sizes, int n_in,
                              void* d_out, int out_size)
{
    const float* x    = (const float*)d_in[0];   // [8, 2048, 512]
    const float* W    = (const float*)d_in[1];   // [512, 1026]
    const float* bias = (const float*)d_in[2];   // [1026]
    float* out = (float*)d_out;                  // [8, 524544]

    cudaFuncSetAttribute(gemm_mma_kernel,
                         cudaFuncAttributeMaxDynamicSharedMemorySize,
                         GEMM_SMEM);

    // 0) prep: bf16 splits + tables + envelope
    split_x_kernel<<<(M_TOTAL * K_DIM) / (256 * 8), 256>>>(x);
    prep_w_kernel<<<(N_PAD * K_DIM + 255) / 256, 256>>>(W);
    tables_kernel<<<4, 256>>>();
    env_kernel<<<(OUT_FULL + 255) / 256, 256>>>();

    // 1) tensor-core (HMMA) GEMM -> g_h
    dim3 g1(N_PAD / 128, M_TOTAL / 128);   // (9, 128)
    gemm_mma_kernel<<<g1, 256, GEMM_SMEM>>>(bias);

    // 2) spectrum -> half-size irfft -> window -> g_frames
    ifft_kernel<<<M_TOTAL, 256>>>();

    // 3) overlap-add * 1/env -> out
    int total = BATCH * OUT_LEN;
    ola_kernel<<<(total + 255) / 256, 256>>>(out);
}